// round 1
// baseline (speedup 1.0000x reference)
#include <cuda_runtime.h>
#include <math.h>

// Shapes (fixed by the problem)
#define Bb   2
#define SS   1024
#define HH   2048
#define NHH  32
#define NKVV 8
#define DD   64
#define IIF  8192
#define TOK  (Bb*SS)          // 2048 tokens
#define LCK  3

// ---------------- scratch (device globals; no allocation allowed) ----------------
__device__ float g_x[TOK * 2 * HH];          // [2048, 4096] concat(e, h)
__device__ float g_qkv[TOK * 3072];          // [2048, 3072] q|k|v pre-rope
__device__ float g_q[Bb * NHH * SS * DD];    // [B,NH,S,D]
__device__ float g_k[Bb * NKVV * SS * DD];   // [B,NKV,S,D]
__device__ float g_v[Bb * NKVV * SS * DD];
__device__ float g_attn[TOK * HH];           // [2048, 2048] attention out (token-major)
__device__ float g_h2[TOK * HH];
__device__ float g_hn[TOK * HH];
__device__ float g_gate[TOK * IIF];
__device__ float g_up[TOK * IIF];

// ---------------- block reduce ----------------
__device__ __forceinline__ float blockReduceSum(float v) {
    __shared__ float red[8];
    int lane = threadIdx.x & 31, w = threadIdx.x >> 5;
#pragma unroll
    for (int o = 16; o; o >>= 1) v += __shfl_xor_sync(0xffffffffu, v, o);
    if (lane == 0) red[w] = v;
    __syncthreads();
    if (w == 0) {
        float t = (lane < 8) ? red[lane] : 0.0f;
#pragma unroll
        for (int o = 4; o; o >>= 1) t += __shfl_xor_sync(0xffffffffu, t, o);
        if (lane == 0) red[0] = t;
    }
    __syncthreads();
    float r = red[0];
    __syncthreads();
    return r;
}

// ---------------- fused RMSNorm(emb) | RMSNorm(hidden) -> concat x ----------------
__global__ __launch_bounds__(256) void rmsnorm_concat_kernel(
    const float* __restrict__ emb, const float* __restrict__ hid,
    const float* __restrict__ w_e, const float* __restrict__ w_h,
    float* __restrict__ x)
{
    int t = blockIdx.x;
    const float* e  = emb + (size_t)t * HH;
    const float* hh = hid + (size_t)t * HH;
    float se = 0.f, sh = 0.f;
    for (int i = threadIdx.x; i < HH; i += 256) {
        float a = e[i];  se += a * a;
        float c = hh[i]; sh += c * c;
    }
    se = blockReduceSum(se);
    sh = blockReduceSum(sh);
    float re = rsqrtf(se / (float)HH + 1e-6f);
    float rh = rsqrtf(sh / (float)HH + 1e-6f);
    float* xr = x + (size_t)t * (2 * HH);
    for (int i = threadIdx.x; i < HH; i += 256) {
        xr[i]      = w_e[i] * e[i]  * re;
        xr[HH + i] = w_h[i] * hh[i] * rh;
    }
}

// ---------------- plain RMSNorm ----------------
__global__ __launch_bounds__(256) void rmsnorm_kernel(
    const float* __restrict__ in, const float* __restrict__ w,
    float* __restrict__ out)
{
    int t = blockIdx.x;
    const float* r = in + (size_t)t * HH;
    float s = 0.f;
    for (int i = threadIdx.x; i < HH; i += 256) { float a = r[i]; s += a * a; }
    s = blockReduceSum(s);
    float inv = rsqrtf(s / (float)HH + 1e-6f);
    float* o = out + (size_t)t * HH;
    for (int i = threadIdx.x; i < HH; i += 256) o[i] = w[i] * r[i] * inv;
}

// ---------------- SGEMM: C[M,N] = A[M,K] * B[N,K]^T (+resid) ----------------
// 128x128 tile, BK=16, 256 threads, 8x8 microtile.
__global__ __launch_bounds__(256) void sgemm_nt(
    const float* __restrict__ A, const float* __restrict__ Bm,
    const float* __restrict__ resid, float* __restrict__ C,
    int ldc, int M, int N, int K, int addResid)
{
    __shared__ float As[16][132];
    __shared__ float Bs[16][132];
    int tid = threadIdx.x;
    int tx = tid & 15, ty = tid >> 4;
    int lr = tid >> 2;          // 0..63
    int lc = (tid & 3) << 2;    // 0,4,8,12
    const float* Ab = A  + (size_t)(blockIdx.y * 128) * K;
    const float* Bb2 = Bm + (size_t)(blockIdx.x * 128) * K;
    float acc[8][8];
#pragma unroll
    for (int i = 0; i < 8; i++)
#pragma unroll
        for (int j = 0; j < 8; j++) acc[i][j] = 0.f;

    for (int k0 = 0; k0 < K; k0 += 16) {
#pragma unroll
        for (int p = 0; p < 2; p++) {
            float4 a = *(const float4*)(Ab + (size_t)(lr + p * 64) * K + k0 + lc);
            As[lc + 0][lr + p * 64] = a.x;
            As[lc + 1][lr + p * 64] = a.y;
            As[lc + 2][lr + p * 64] = a.z;
            As[lc + 3][lr + p * 64] = a.w;
            float4 b = *(const float4*)(Bb2 + (size_t)(lr + p * 64) * K + k0 + lc);
            Bs[lc + 0][lr + p * 64] = b.x;
            Bs[lc + 1][lr + p * 64] = b.y;
            Bs[lc + 2][lr + p * 64] = b.z;
            Bs[lc + 3][lr + p * 64] = b.w;
        }
        __syncthreads();
#pragma unroll
        for (int kk = 0; kk < 16; kk++) {
            float af[8], bf[8];
            *(float4*)&af[0] = *(const float4*)&As[kk][ty * 4];
            *(float4*)&af[4] = *(const float4*)&As[kk][64 + ty * 4];
            *(float4*)&bf[0] = *(const float4*)&Bs[kk][tx * 4];
            *(float4*)&bf[4] = *(const float4*)&Bs[kk][64 + tx * 4];
#pragma unroll
            for (int i = 0; i < 8; i++)
#pragma unroll
                for (int j = 0; j < 8; j++)
                    acc[i][j] += af[i] * bf[j];
        }
        __syncthreads();
    }
#pragma unroll
    for (int i = 0; i < 8; i++) {
        int r = blockIdx.y * 128 + ((i < 4) ? (ty * 4 + i) : (64 + ty * 4 + i - 4));
#pragma unroll
        for (int jh = 0; jh < 2; jh++) {
            int c = blockIdx.x * 128 + ((jh == 0) ? (tx * 4) : (64 + tx * 4));
            float4 v;
            v.x = acc[i][jh * 4 + 0];
            v.y = acc[i][jh * 4 + 1];
            v.z = acc[i][jh * 4 + 2];
            v.w = acc[i][jh * 4 + 3];
            if (addResid) {
                float4 rv = *(const float4*)(resid + (size_t)r * ldc + c);
                v.x += rv.x; v.y += rv.y; v.z += rv.z; v.w += rv.w;
            }
            *(float4*)(C + (size_t)r * ldc + c) = v;
        }
    }
}

// ---------------- RoPE + layout transform ----------------
__global__ __launch_bounds__(256) void rope_kernel(
    const float* __restrict__ qkv, const int* __restrict__ pos_ids,
    float* __restrict__ q, float* __restrict__ k, float* __restrict__ v)
{
    int t = blockIdx.x;              // token
    int b = t >> 10, s = t & 1023;
    float pos = (float)(pos_ids[t] + LCK);
    const float* row = qkv + (size_t)t * 3072;
    const float lg = logf(10000.0f) / 32.0f;

    for (int p = threadIdx.x; p < 1024 + 256; p += 256) {
        const float* src; float* dst; int hh, d;
        if (p < 1024) {
            hh = p >> 5; d = p & 31;
            src = row + hh * 64;
            dst = q + (((size_t)b * NHH + hh) * SS + s) * 64;
        } else {
            int pp = p - 1024;
            hh = pp >> 5; d = pp & 31;
            src = row + 2048 + hh * 64;
            dst = k + (((size_t)b * NKVV + hh) * SS + s) * 64;
        }
        float invf = expf(-(float)d * lg);
        float ang = pos * invf;
        float c = cosf(ang), sn = sinf(ang);
        float x0 = src[d], x1 = src[d + 32];
        dst[d]      = x0 * c - x1 * sn;
        dst[d + 32] = x1 * c + x0 * sn;
    }
    for (int p = threadIdx.x; p < 512; p += 256) {
        int hh = p >> 6, d = p & 63;
        v[(((size_t)b * NKVV + hh) * SS + s) * 64 + d] = row[2560 + p];
    }
}

// ---------------- attention (flash-style online softmax) ----------------
// grid (S/64, NH, B), 256 threads, dynamic smem.
__global__ __launch_bounds__(256) void attn_kernel(
    const float* __restrict__ q, const float* __restrict__ cache_k,
    const float* __restrict__ cache_v, const float* __restrict__ kcur,
    const float* __restrict__ vcur, float* __restrict__ out)
{
    extern __shared__ float sm[];
    float (*Qs)[68] = (float (*)[68])sm;                    // [d][i]
    float (*Ks)[68] = (float (*)[68])(sm + 64 * 68);        // [d][j]
    float (*Vs)[68] = (float (*)[68])(sm + 2 * 64 * 68);    // [j][d]
    float (*sc)[68] = (float (*)[68])(sm + 3 * 64 * 68);    // [i][j]
    float* m_s  = sm + 4 * 64 * 68;
    float* l_s  = m_s + 64;
    float* cr_s = l_s + 64;

    int tid = threadIdx.x;
    int tx = tid & 15, ty = tid >> 4;
    int lr = tid >> 2, lc = (tid & 3) << 2;
    int qt = blockIdx.x, h = blockIdx.y, b = blockIdx.z;
    int q0 = qt * 64;
    size_t bh = (size_t)b * NHH + h;
    const float scale = 0.125f;

    // load Q transposed
    {
        const float* qb = q + (bh * SS + q0 + lr) * 64;
#pragma unroll
        for (int dblk = 0; dblk < 4; dblk++) {
            int d = lc + dblk * 16;
            float4 t4 = *(const float4*)(qb + d);
            Qs[d + 0][lr] = t4.x; Qs[d + 1][lr] = t4.y;
            Qs[d + 2][lr] = t4.z; Qs[d + 3][lr] = t4.w;
        }
    }
    if (tid < 64) { m_s[tid] = -1e30f; l_s[tid] = 0.f; }

    float acc[4][4];
#pragma unroll
    for (int i = 0; i < 4; i++)
#pragma unroll
        for (int j = 0; j < 4; j++) acc[i][j] = 0.f;

    const float* k0p = cache_k + bh * SS * 64;
    const float* v0p = cache_v + bh * SS * 64;

    for (int kb = 0; kb <= qt; kb++) {
        __syncthreads();
        {
            const float* kp = k0p + (size_t)(kb * 64 + lr) * 64;
            const float* vp = v0p + (size_t)(kb * 64 + lr) * 64;
#pragma unroll
            for (int dblk = 0; dblk < 4; dblk++) {
                int d = lc + dblk * 16;
                float4 k4 = *(const float4*)(kp + d);
                Ks[d + 0][lr] = k4.x; Ks[d + 1][lr] = k4.y;
                Ks[d + 2][lr] = k4.z; Ks[d + 3][lr] = k4.w;
                float4 v4 = *(const float4*)(vp + d);
                *(float4*)&Vs[lr][d] = v4;
            }
        }
        __syncthreads();

        float sreg[4][4];
#pragma unroll
        for (int i = 0; i < 4; i++)
#pragma unroll
            for (int j = 0; j < 4; j++) sreg[i][j] = 0.f;
#pragma unroll 4
        for (int dk = 0; dk < 64; dk++) {
            float4 qa = *(const float4*)&Qs[dk][ty * 4];
            float4 ka = *(const float4*)&Ks[dk][tx * 4];
            float qf[4] = {qa.x, qa.y, qa.z, qa.w};
            float kf[4] = {ka.x, ka.y, ka.z, ka.w};
#pragma unroll
            for (int i = 0; i < 4; i++)
#pragma unroll
                for (int j = 0; j < 4; j++)
                    sreg[i][j] += qf[i] * kf[j];
        }
        bool diag = (kb == qt);
#pragma unroll
        for (int i = 0; i < 4; i++) {
#pragma unroll
            for (int j = 0; j < 4; j++) {
                float vv = sreg[i][j] * scale;
                if (diag && (tx * 4 + j) > (ty * 4 + i)) vv = -1e30f;
                sreg[i][j] = vv;
            }
            float4 st; st.x = sreg[i][0]; st.y = sreg[i][1]; st.z = sreg[i][2]; st.w = sreg[i][3];
            *(float4*)&sc[ty * 4 + i][tx * 4] = st;
        }
        __syncthreads();

        // per-row online softmax stats (4 lanes per row)
        {
            int rr = lr, lane = tid & 3;
            float mx = -1e30f;
#pragma unroll
            for (int j2 = 0; j2 < 16; j2++) mx = fmaxf(mx, sc[rr][lane * 16 + j2]);
            mx = fmaxf(mx, __shfl_xor_sync(0xffffffffu, mx, 1));
            mx = fmaxf(mx, __shfl_xor_sync(0xffffffffu, mx, 2));
            float mold = m_s[rr];
            float nm = fmaxf(mold, mx);
            float sum = 0.f;
#pragma unroll
            for (int j2 = 0; j2 < 16; j2++) {
                float p = __expf(sc[rr][lane * 16 + j2] - nm);
                sc[rr][lane * 16 + j2] = p;
                sum += p;
            }
            sum += __shfl_xor_sync(0xffffffffu, sum, 1);
            sum += __shfl_xor_sync(0xffffffffu, sum, 2);
            if (lane == 0) {
                float corr = __expf(mold - nm);
                l_s[rr] = l_s[rr] * corr + sum;
                m_s[rr] = nm;
                cr_s[rr] = corr;
            }
        }
        __syncthreads();

#pragma unroll
        for (int i = 0; i < 4; i++) {
            float cf = cr_s[ty * 4 + i];
#pragma unroll
            for (int j = 0; j < 4; j++) acc[i][j] *= cf;
        }
#pragma unroll 2
        for (int j = 0; j < 64; j++) {
            float4 vv = *(const float4*)&Vs[j][tx * 4];
            float vf[4] = {vv.x, vv.y, vv.z, vv.w};
#pragma unroll
            for (int i = 0; i < 4; i++) {
                float p = sc[ty * 4 + i][j];
#pragma unroll
                for (int jj = 0; jj < 4; jj++) acc[i][jj] += p * vf[jj];
            }
        }
    }

    // ---- 3 extra (diagonal) keys: cache_k[1], cache_k[2], current k ----
    __syncthreads();
    {
        int rr = lr, lane = tid & 3;
        if (lane < 3) {
            int s = q0 + rr;
            const float* kvec;
            if (lane < 2)
                kvec = cache_k + (((size_t)(1 + lane) * Bb * NHH + bh) * SS + s) * 64;
            else
                kvec = kcur + (((size_t)b * NKVV + (h >> 2)) * SS + s) * 64;
            float dot = 0.f;
#pragma unroll 8
            for (int d = 0; d < 64; d++) dot += Qs[d][rr] * kvec[d];
            sc[rr][lane] = dot * scale;
        }
    }
    __syncthreads();
    if ((tid & 3) == 0) {
        int rr = lr;
        float mold = m_s[rr];
        float mx = mold;
#pragma unroll
        for (int n = 0; n < 3; n++) mx = fmaxf(mx, sc[rr][n]);
        float sum = 0.f;
#pragma unroll
        for (int n = 0; n < 3; n++) {
            float p = __expf(sc[rr][n] - mx);
            sc[rr][n] = p;
            sum += p;
        }
        float corr = __expf(mold - mx);
        l_s[rr] = l_s[rr] * corr + sum;
        m_s[rr] = mx;
        cr_s[rr] = corr;
    }
    __syncthreads();
#pragma unroll
    for (int i = 0; i < 4; i++) {
        float cf = cr_s[ty * 4 + i];
#pragma unroll
        for (int j = 0; j < 4; j++) acc[i][j] *= cf;
    }
#pragma unroll
    for (int i = 0; i < 4; i++) {
        int s = q0 + ty * 4 + i;
#pragma unroll
        for (int n = 0; n < 3; n++) {
            const float* vvec = (n < 2)
                ? cache_v + (((size_t)(1 + n) * Bb * NHH + bh) * SS + s) * 64
                : vcur + (((size_t)b * NKVV + (h >> 2)) * SS + s) * 64;
            float p = sc[ty * 4 + i][n];
            float4 vv = *(const float4*)(vvec + tx * 4);
            acc[i][0] += p * vv.x; acc[i][1] += p * vv.y;
            acc[i][2] += p * vv.z; acc[i][3] += p * vv.w;
        }
    }
    // finalize
#pragma unroll
    for (int i = 0; i < 4; i++) {
        int s = q0 + ty * 4 + i;
        float inv = 1.0f / l_s[ty * 4 + i];
        float4 o;
        o.x = acc[i][0] * inv; o.y = acc[i][1] * inv;
        o.z = acc[i][2] * inv; o.w = acc[i][3] * inv;
        *(float4*)(out + ((size_t)(b * SS + s)) * HH + h * 64 + tx * 4) = o;
    }
}

// ---------------- SiLU(gate)*up ----------------
__global__ __launch_bounds__(256) void silu_mul_kernel(
    const float* __restrict__ g, const float* __restrict__ u,
    float* __restrict__ o, int n)
{
    int i = blockIdx.x * 256 + threadIdx.x;
    if (i < n) {
        float x = g[i];
        float s = 1.0f / (1.0f + expf(-x));
        o[i] = x * s * u[i];
    }
}

// ---------------- launcher ----------------
extern "C" void kernel_launch(void* const* d_in, const int* in_sizes, int n_in,
                              void* d_out, int out_size)
{
    const float* input_emb     = (const float*)d_in[0];
    const float* hidden_states = (const float*)d_in[1];
    const float* cache_k       = (const float*)d_in[2];
    const float* cache_v       = (const float*)d_in[3];
    // d_in[4] = attention_mask (known causal tril; not read)
    const int*   position_ids  = (const int*)d_in[5];
    const float* wq            = (const float*)d_in[6];
    const float* wk            = (const float*)d_in[7];
    const float* wv            = (const float*)d_in[8];
    const float* wo            = (const float*)d_in[9];
    const float* w_gate        = (const float*)d_in[10];
    const float* w_up          = (const float*)d_in[11];
    const float* w_down        = (const float*)d_in[12];
    const float* hidden_norm_w = (const float*)d_in[13];
    const float* input_ln_w    = (const float*)d_in[14];
    const float* post_ln_w     = (const float*)d_in[15];
    float* out = (float*)d_out;

    float *x, *qkv, *q, *k, *v, *attn, *h2, *hn, *gate, *up;
    cudaGetSymbolAddress((void**)&x,    g_x);
    cudaGetSymbolAddress((void**)&qkv,  g_qkv);
    cudaGetSymbolAddress((void**)&q,    g_q);
    cudaGetSymbolAddress((void**)&k,    g_k);
    cudaGetSymbolAddress((void**)&v,    g_v);
    cudaGetSymbolAddress((void**)&attn, g_attn);
    cudaGetSymbolAddress((void**)&h2,   g_h2);
    cudaGetSymbolAddress((void**)&hn,   g_hn);
    cudaGetSymbolAddress((void**)&gate, g_gate);
    cudaGetSymbolAddress((void**)&up,   g_up);

    // 1. norms + concat
    rmsnorm_concat_kernel<<<TOK, 256>>>(input_emb, hidden_states,
                                        input_ln_w, hidden_norm_w, x);
    // 2. QKV GEMMs (shared x, ldc = 3072)
    sgemm_nt<<<dim3(2048 / 128, TOK / 128), 256>>>(x, wq, nullptr, qkv,        3072, TOK, 2048, 4096, 0);
    sgemm_nt<<<dim3(512  / 128, TOK / 128), 256>>>(x, wk, nullptr, qkv + 2048, 3072, TOK, 512,  4096, 0);
    sgemm_nt<<<dim3(512  / 128, TOK / 128), 256>>>(x, wv, nullptr, qkv + 2560, 3072, TOK, 512,  4096, 0);
    // 3. RoPE + reshape
    rope_kernel<<<TOK, 256>>>(qkv, position_ids, q, k, v);
    // 4. attention
    const int attn_smem = (4 * 64 * 68 + 3 * 64) * (int)sizeof(float);
    cudaFuncSetAttribute(attn_kernel, cudaFuncAttributeMaxDynamicSharedMemorySize, attn_smem);
    attn_kernel<<<dim3(SS / 64, NHH, Bb), 256, attn_smem>>>(q, cache_k, cache_v, k, v, attn);
    // 5. out projection + residual
    sgemm_nt<<<dim3(16, 16), 256>>>(attn, wo, hidden_states, h2, 2048, TOK, 2048, 2048, 1);
    // 6. post-attn norm
    rmsnorm_kernel<<<TOK, 256>>>(h2, post_ln_w, hn);
    // 7. MLP
    sgemm_nt<<<dim3(IIF / 128, 16), 256>>>(hn, w_gate, nullptr, gate, IIF, TOK, IIF, 2048, 0);
    sgemm_nt<<<dim3(IIF / 128, 16), 256>>>(hn, w_up,   nullptr, up,   IIF, TOK, IIF, 2048, 0);
    silu_mul_kernel<<<(TOK * IIF + 255) / 256, 256>>>(gate, up, gate, TOK * IIF);
    // 8. down projection + residual -> final output
    sgemm_nt<<<dim3(16, 16), 256>>>(gate, w_down, h2, out, 2048, TOK, 2048, IIF, 1);
    (void)in_sizes; (void)n_in; (void)out_size;
}

// round 5
// speedup vs baseline: 2.2740x; 2.2740x over previous
#include <cuda_runtime.h>
#include <cuda_bf16.h>
#include <cstdint>
#include <math.h>

// Shapes (fixed by the problem)
#define Bb   2
#define SS   1024
#define HH   2048
#define NHH  32
#define NKVV 8
#define DD   64
#define IIF  8192
#define TOK  (Bb*SS)          // 2048 tokens
#define LCK  3

// ================= PTX helpers (arch-neutral: sm_80+ instructions only) ======
__device__ __forceinline__ uint32_t smem_to_u32(const void* p) {
    uint32_t a;
    asm("{ .reg .u64 t; cvta.to.shared.u64 t, %1; cvt.u32.u64 %0, t; }" : "=r"(a) : "l"(p));
    return a;
}

__device__ __forceinline__ void cp16(uint32_t s, const void* g) {
    asm volatile("cp.async.cg.shared.global [%0], [%1], 16;" :: "r"(s), "l"(g) : "memory");
}
#define CP_COMMIT() asm volatile("cp.async.commit_group;" ::: "memory")
#define CP_WAIT(n)  asm volatile("cp.async.wait_group %0;" :: "n"(n) : "memory")

__device__ __forceinline__ void ldsm4(uint32_t* r, uint32_t addr) {
    asm volatile("ldmatrix.sync.aligned.m8n8.x4.shared.b16 {%0,%1,%2,%3}, [%4];"
                 : "=r"(r[0]), "=r"(r[1]), "=r"(r[2]), "=r"(r[3]) : "r"(addr));
}

#define MMA_BF16(c, a, b0, b1)                                            \
    asm volatile("mma.sync.aligned.m16n8k16.row.col.f32.bf16.bf16.f32 "   \
        "{%0,%1,%2,%3}, {%4,%5,%6,%7}, {%8,%9}, {%0,%1,%2,%3};"           \
        : "+f"((c)[0]), "+f"((c)[1]), "+f"((c)[2]), "+f"((c)[3])          \
        : "r"((a)[0]), "r"((a)[1]), "r"((a)[2]), "r"((a)[3]),             \
          "r"(b0), "r"(b1))

// ================= scratch (device globals) =================
__device__ __nv_bfloat16 g_xhi[TOK * 4096],   g_xlo[TOK * 4096];
__device__ __nv_bfloat16 g_wqkv_hi[3072 * 4096],  g_wqkv_lo[3072 * 4096];
__device__ __nv_bfloat16 g_wo_hi[2048 * 2048],    g_wo_lo[2048 * 2048];
__device__ __nv_bfloat16 g_wgu_hi[16384 * 2048],  g_wgu_lo[16384 * 2048];
__device__ __nv_bfloat16 g_wdn_hi[2048 * 8192],   g_wdn_lo[2048 * 8192];
__device__ __nv_bfloat16 g_ahi[TOK * 2048],   g_alo[TOK * 2048];   // attention out
__device__ __nv_bfloat16 g_hnhi[TOK * 2048],  g_hnlo[TOK * 2048];
__device__ __nv_bfloat16 g_acthi[TOK * 8192], g_actlo[TOK * 8192];
__device__ float g_qkv[TOK * 3072];
__device__ float g_q[Bb * NHH * SS * DD];
__device__ float g_k[Bb * NKVV * SS * DD];
__device__ float g_v[Bb * NKVV * SS * DD];
__device__ float g_h2[TOK * 2048];
__device__ float g_gu[TOK * 16384];

__device__ __forceinline__ void split2(float x, __nv_bfloat16& h, __nv_bfloat16& l) {
    h = __float2bfloat16(x);
    l = __float2bfloat16(x - __bfloat162float(h));
}

// ================= tensor-core GEMM (mma.sync bf16, 3-pass split) ============
// C[M,N] = A[M,K] * B[N,K]^T (+resid).  Tile 128x128, BK=32, 256 threads.
// smem rows padded to 80 bytes (40 bf16): LDSM granule stride 5 mod 8 => no
// bank conflicts. 4-stage cp.async pipeline.
#define ROWB       80
#define MAT_BYTES  (128 * ROWB)      // 10240
#define STG_BYTES  (4 * MAT_BYTES)   // 40960  (Ah | Al | Bh | Bl)
#define GEMM_DSMEM (4 * STG_BYTES)   // 163840

__device__ __forceinline__ void stage_mat(uint32_t smat, const __nv_bfloat16* __restrict__ src,
                                          int row0, int K, int k0, int tid) {
#pragma unroll
    for (int h = 0; h < 2; h++) {
        int idx = tid + h * 256;
        int row = idx >> 2, c = idx & 3;
        cp16(smat + row * ROWB + c * 16,
             src + (size_t)(row0 + row) * K + k0 + c * 8);
    }
}

__global__ __launch_bounds__(256, 1) void gemm_mma(
    const __nv_bfloat16* __restrict__ Ahi, const __nv_bfloat16* __restrict__ Alo,
    const __nv_bfloat16* __restrict__ Bhi, const __nv_bfloat16* __restrict__ Blo,
    const float* __restrict__ resid, float* __restrict__ C,
    int ldc, int K, int addResid)
{
    extern __shared__ char dsm[];
    uint32_t sbase = smem_to_u32(dsm);
    int tid = threadIdx.x, wid = tid >> 5, lane = tid & 31;
    int m0 = blockIdx.y * 128, n0 = blockIdx.x * 128;
    int wm = (wid & 1) * 64;        // warp row offset within tile
    int wn = (wid >> 1) * 32;       // warp col offset within tile
    int tile = lane >> 3, r = lane & 7;

    float acc[4][4][4];
#pragma unroll
    for (int f = 0; f < 4; f++)
#pragma unroll
        for (int n = 0; n < 4; n++)
#pragma unroll
            for (int e = 0; e < 4; e++) acc[f][n][e] = 0.f;

    int nK = K >> 5;
    // prologue: prefetch 3 stages
#pragma unroll
    for (int s = 0; s < 3; s++) {
        uint32_t so = sbase + s * STG_BYTES;
        int k0 = s << 5;
        stage_mat(so,                 Ahi, m0, K, k0, tid);
        stage_mat(so + MAT_BYTES,     Alo, m0, K, k0, tid);
        stage_mat(so + 2 * MAT_BYTES, Bhi, n0, K, k0, tid);
        stage_mat(so + 3 * MAT_BYTES, Blo, n0, K, k0, tid);
        CP_COMMIT();
    }

    // lane-dependent LDSM offsets (row-part precomputed)
    uint32_t aoff = (uint32_t)((((tile & 1) << 3) + r) * ROWB + ((tile >> 1) << 4)); // + f*16*ROWB + kk*2
    uint32_t boff = (uint32_t)((((tile >> 1) << 3) + r) * ROWB + ((tile & 1) << 4)); // + g*16*ROWB + kk*2

    for (int ks = 0; ks < nK; ks++) {
        if (ks + 3 <= nK)      { CP_WAIT(2); }
        else if (ks + 2 <= nK) { CP_WAIT(1); }
        else                   { CP_WAIT(0); }
        __syncthreads();

        uint32_t so = sbase + (ks & 3) * STG_BYTES;
        uint32_t aHb = so + (uint32_t)(wm * ROWB);
        uint32_t aLb = aHb + MAT_BYTES;
        uint32_t bHb = so + 2 * MAT_BYTES + (uint32_t)(wn * ROWB);
        uint32_t bLb = bHb + MAT_BYTES;

#pragma unroll
        for (int kk = 0; kk < 2; kk++) {        // two k16 steps per BK=32
            uint32_t Ah[4][4], Al[4][4], Bh[2][4], Bl[2][4];
            uint32_t kadd = (uint32_t)(kk << 5);  // kk*16 elements * 2 bytes
#pragma unroll
            for (int f = 0; f < 4; f++) {
                uint32_t off = aoff + (uint32_t)(f * 16 * ROWB) + kadd;
                ldsm4(Ah[f], aHb + off);
                ldsm4(Al[f], aLb + off);
            }
#pragma unroll
            for (int g = 0; g < 2; g++) {
                uint32_t off = boff + (uint32_t)(g * 16 * ROWB) + kadd;
                ldsm4(Bh[g], bHb + off);
                ldsm4(Bl[g], bLb + off);
            }
#pragma unroll
            for (int f = 0; f < 4; f++) {
#pragma unroll
                for (int n = 0; n < 4; n++) {
                    const uint32_t* bh = &Bh[n >> 1][(n & 1) * 2];
                    const uint32_t* bl = &Bl[n >> 1][(n & 1) * 2];
                    MMA_BF16(acc[f][n], Ah[f], bh[0], bh[1]);
                    MMA_BF16(acc[f][n], Ah[f], bl[0], bl[1]);
                    MMA_BF16(acc[f][n], Al[f], bh[0], bh[1]);
                }
            }
        }
        __syncthreads();
        int pf = ks + 3;
        if (pf < nK) {
            uint32_t sp = sbase + (pf & 3) * STG_BYTES;
            int k0 = pf << 5;
            stage_mat(sp,                 Ahi, m0, K, k0, tid);
            stage_mat(sp + MAT_BYTES,     Alo, m0, K, k0, tid);
            stage_mat(sp + 2 * MAT_BYTES, Bhi, n0, K, k0, tid);
            stage_mat(sp + 3 * MAT_BYTES, Blo, n0, K, k0, tid);
            CP_COMMIT();
        }
    }

    // epilogue: c frag (m16n8): c0,c1 -> row t/4, cols 2(t%4)+{0,1}; c2,c3 -> row+8
    int rr = lane >> 2, cc = (lane & 3) * 2;
#pragma unroll
    for (int f = 0; f < 4; f++) {
#pragma unroll
        for (int n = 0; n < 4; n++) {
            int m = m0 + wm + f * 16 + rr;
            int c = n0 + wn + n * 8 + cc;
            size_t i0 = (size_t)m * ldc + c;
            size_t i1 = (size_t)(m + 8) * ldc + c;
            float2 v0 = make_float2(acc[f][n][0], acc[f][n][1]);
            float2 v1 = make_float2(acc[f][n][2], acc[f][n][3]);
            if (addResid) {
                float2 r0 = *(const float2*)(resid + i0);
                float2 r1 = *(const float2*)(resid + i1);
                v0.x += r0.x; v0.y += r0.y;
                v1.x += r1.x; v1.y += r1.y;
            }
            *(float2*)(C + i0) = v0;
            *(float2*)(C + i1) = v1;
        }
    }
}

// ================= small kernels =================
__device__ __forceinline__ float blockReduceSum(float v) {
    __shared__ float red[8];
    int lane = threadIdx.x & 31, w = threadIdx.x >> 5;
#pragma unroll
    for (int o = 16; o; o >>= 1) v += __shfl_xor_sync(0xffffffffu, v, o);
    if (lane == 0) red[w] = v;
    __syncthreads();
    if (w == 0) {
        float t = (lane < 8) ? red[lane] : 0.0f;
#pragma unroll
        for (int o = 4; o; o >>= 1) t += __shfl_xor_sync(0xffffffffu, t, o);
        if (lane == 0) red[0] = t;
    }
    __syncthreads();
    float r = red[0];
    __syncthreads();
    return r;
}

// fused RMSNorm(emb) | RMSNorm(hidden) -> concat split bf16 pair
__global__ __launch_bounds__(256) void rmsnorm_concat_kernel(
    const float* __restrict__ emb, const float* __restrict__ hid,
    const float* __restrict__ w_e, const float* __restrict__ w_h,
    __nv_bfloat16* __restrict__ xhi, __nv_bfloat16* __restrict__ xlo)
{
    int t = blockIdx.x;
    const float* e  = emb + (size_t)t * HH;
    const float* hh = hid + (size_t)t * HH;
    float se = 0.f, sh = 0.f;
    for (int i = threadIdx.x; i < HH; i += 256) {
        float a = e[i];  se += a * a;
        float c = hh[i]; sh += c * c;
    }
    se = blockReduceSum(se);
    sh = blockReduceSum(sh);
    float re = rsqrtf(se / (float)HH + 1e-6f);
    float rh = rsqrtf(sh / (float)HH + 1e-6f);
    size_t ro = (size_t)t * 4096;
    for (int i = threadIdx.x; i < HH; i += 256) {
        __nv_bfloat16 hv, lv;
        split2(w_e[i] * e[i] * re, hv, lv);
        xhi[ro + i] = hv; xlo[ro + i] = lv;
        split2(w_h[i] * hh[i] * rh, hv, lv);
        xhi[ro + HH + i] = hv; xlo[ro + HH + i] = lv;
    }
}

// RMSNorm -> split bf16 pair
__global__ __launch_bounds__(256) void rmsnorm_split_kernel(
    const float* __restrict__ in, const float* __restrict__ w,
    __nv_bfloat16* __restrict__ ohi, __nv_bfloat16* __restrict__ olo)
{
    int t = blockIdx.x;
    const float* r = in + (size_t)t * HH;
    float s = 0.f;
    for (int i = threadIdx.x; i < HH; i += 256) { float a = r[i]; s += a * a; }
    s = blockReduceSum(s);
    float inv = rsqrtf(s / (float)HH + 1e-6f);
    size_t ro = (size_t)t * HH;
    for (int i = threadIdx.x; i < HH; i += 256) {
        __nv_bfloat16 hv, lv;
        split2(w[i] * r[i] * inv, hv, lv);
        ohi[ro + i] = hv; olo[ro + i] = lv;
    }
}

// fp32 -> bf16 hi/lo split (weights)
__global__ __launch_bounds__(256) void convert_split_kernel(
    const float* __restrict__ src, __nv_bfloat16* __restrict__ hi,
    __nv_bfloat16* __restrict__ lo, int n)
{
    int i = (blockIdx.x * 256 + threadIdx.x) * 4;
    if (i < n) {
        float4 v = *(const float4*)(src + i);
        __nv_bfloat16 h0, l0, h1, l1, h2, l2, h3, l3;
        split2(v.x, h0, l0); split2(v.y, h1, l1);
        split2(v.z, h2, l2); split2(v.w, h3, l3);
        __nv_bfloat162* ph = (__nv_bfloat162*)(hi + i);
        __nv_bfloat162* pl = (__nv_bfloat162*)(lo + i);
        ph[0] = __nv_bfloat162(h0, h1); ph[1] = __nv_bfloat162(h2, h3);
        pl[0] = __nv_bfloat162(l0, l1); pl[1] = __nv_bfloat162(l2, l3);
    }
}

// RoPE + layout transform
__global__ __launch_bounds__(256) void rope_kernel(
    const float* __restrict__ qkv, const int* __restrict__ pos_ids,
    float* __restrict__ q, float* __restrict__ k, float* __restrict__ v)
{
    int t = blockIdx.x;
    int b = t >> 10, s = t & 1023;
    float pos = (float)(pos_ids[t] + LCK);
    const float* row = qkv + (size_t)t * 3072;
    const float lg = logf(10000.0f) / 32.0f;

    for (int p = threadIdx.x; p < 1024 + 256; p += 256) {
        const float* src; float* dst; int hh, d;
        if (p < 1024) {
            hh = p >> 5; d = p & 31;
            src = row + hh * 64;
            dst = q + (((size_t)b * NHH + hh) * SS + s) * 64;
        } else {
            int pp = p - 1024;
            hh = pp >> 5; d = pp & 31;
            src = row + 2048 + hh * 64;
            dst = k + (((size_t)b * NKVV + hh) * SS + s) * 64;
        }
        float invf = expf(-(float)d * lg);
        float ang = pos * invf;
        float c = cosf(ang), sn = sinf(ang);
        float x0 = src[d], x1 = src[d + 32];
        dst[d]      = x0 * c - x1 * sn;
        dst[d + 32] = x1 * c + x0 * sn;
    }
    for (int p = threadIdx.x; p < 512; p += 256) {
        int hh = p >> 6, d = p & 63;
        v[(((size_t)b * NKVV + hh) * SS + s) * 64 + d] = row[2560 + p];
    }
}

// attention (flash-style online softmax); writes bf16 hi/lo split output
__global__ __launch_bounds__(256) void attn_kernel(
    const float* __restrict__ q, const float* __restrict__ cache_k,
    const float* __restrict__ cache_v, const float* __restrict__ kcur,
    const float* __restrict__ vcur,
    __nv_bfloat16* __restrict__ ohi, __nv_bfloat16* __restrict__ olo)
{
    extern __shared__ float sm[];
    float (*Qs)[68] = (float (*)[68])sm;
    float (*Ks)[68] = (float (*)[68])(sm + 64 * 68);
    float (*Vs)[68] = (float (*)[68])(sm + 2 * 64 * 68);
    float (*sc)[68] = (float (*)[68])(sm + 3 * 64 * 68);
    float* m_s  = sm + 4 * 64 * 68;
    float* l_s  = m_s + 64;
    float* cr_s = l_s + 64;

    int tid = threadIdx.x;
    int tx = tid & 15, ty = tid >> 4;
    int lr = tid >> 2, lc = (tid & 3) << 2;
    int qt = blockIdx.x, h = blockIdx.y, b = blockIdx.z;
    int q0 = qt * 64;
    size_t bh = (size_t)b * NHH + h;
    const float scale = 0.125f;

    {
        const float* qb = q + (bh * SS + q0 + lr) * 64;
#pragma unroll
        for (int dblk = 0; dblk < 4; dblk++) {
            int d = lc + dblk * 16;
            float4 t4 = *(const float4*)(qb + d);
            Qs[d + 0][lr] = t4.x; Qs[d + 1][lr] = t4.y;
            Qs[d + 2][lr] = t4.z; Qs[d + 3][lr] = t4.w;
        }
    }
    if (tid < 64) { m_s[tid] = -1e30f; l_s[tid] = 0.f; }

    float acc[4][4];
#pragma unroll
    for (int i = 0; i < 4; i++)
#pragma unroll
        for (int j = 0; j < 4; j++) acc[i][j] = 0.f;

    const float* k0p = cache_k + bh * SS * 64;
    const float* v0p = cache_v + bh * SS * 64;

    for (int kb = 0; kb <= qt; kb++) {
        __syncthreads();
        {
            const float* kp = k0p + (size_t)(kb * 64 + lr) * 64;
            const float* vp = v0p + (size_t)(kb * 64 + lr) * 64;
#pragma unroll
            for (int dblk = 0; dblk < 4; dblk++) {
                int d = lc + dblk * 16;
                float4 k4 = *(const float4*)(kp + d);
                Ks[d + 0][lr] = k4.x; Ks[d + 1][lr] = k4.y;
                Ks[d + 2][lr] = k4.z; Ks[d + 3][lr] = k4.w;
                float4 v4 = *(const float4*)(vp + d);
                *(float4*)&Vs[lr][d] = v4;
            }
        }
        __syncthreads();

        float sreg[4][4];
#pragma unroll
        for (int i = 0; i < 4; i++)
#pragma unroll
            for (int j = 0; j < 4; j++) sreg[i][j] = 0.f;
#pragma unroll 4
        for (int dk = 0; dk < 64; dk++) {
            float4 qa = *(const float4*)&Qs[dk][ty * 4];
            float4 ka = *(const float4*)&Ks[dk][tx * 4];
            float qf[4] = {qa.x, qa.y, qa.z, qa.w};
            float kf[4] = {ka.x, ka.y, ka.z, ka.w};
#pragma unroll
            for (int i = 0; i < 4; i++)
#pragma unroll
                for (int j = 0; j < 4; j++)
                    sreg[i][j] += qf[i] * kf[j];
        }
        bool diag = (kb == qt);
#pragma unroll
        for (int i = 0; i < 4; i++) {
#pragma unroll
            for (int j = 0; j < 4; j++) {
                float vv = sreg[i][j] * scale;
                if (diag && (tx * 4 + j) > (ty * 4 + i)) vv = -1e30f;
                sreg[i][j] = vv;
            }
            float4 st; st.x = sreg[i][0]; st.y = sreg[i][1]; st.z = sreg[i][2]; st.w = sreg[i][3];
            *(float4*)&sc[ty * 4 + i][tx * 4] = st;
        }
        __syncthreads();

        {
            int rr = lr, lane = tid & 3;
            float mx = -1e30f;
#pragma unroll
            for (int j2 = 0; j2 < 16; j2++) mx = fmaxf(mx, sc[rr][lane * 16 + j2]);
            mx = fmaxf(mx, __shfl_xor_sync(0xffffffffu, mx, 1));
            mx = fmaxf(mx, __shfl_xor_sync(0xffffffffu, mx, 2));
            float mold = m_s[rr];
            float nm = fmaxf(mold, mx);
            float sum = 0.f;
#pragma unroll
            for (int j2 = 0; j2 < 16; j2++) {
                float p = __expf(sc[rr][lane * 16 + j2] - nm);
                sc[rr][lane * 16 + j2] = p;
                sum += p;
            }
            sum += __shfl_xor_sync(0xffffffffu, sum, 1);
            sum += __shfl_xor_sync(0xffffffffu, sum, 2);
            if (lane == 0) {
                float corr = __expf(mold - nm);
                l_s[rr] = l_s[rr] * corr + sum;
                m_s[rr] = nm;
                cr_s[rr] = corr;
            }
        }
        __syncthreads();

#pragma unroll
        for (int i = 0; i < 4; i++) {
            float cf = cr_s[ty * 4 + i];
#pragma unroll
            for (int j = 0; j < 4; j++) acc[i][j] *= cf;
        }
#pragma unroll 2
        for (int j = 0; j < 64; j++) {
            float4 vv = *(const float4*)&Vs[j][tx * 4];
            float vf[4] = {vv.x, vv.y, vv.z, vv.w};
#pragma unroll
            for (int i = 0; i < 4; i++) {
                float p = sc[ty * 4 + i][j];
#pragma unroll
                for (int jj = 0; jj < 4; jj++) acc[i][jj] += p * vf[jj];
            }
        }
    }

    __syncthreads();
    {
        int rr = lr, lane = tid & 3;
        if (lane < 3) {
            int s = q0 + rr;
            const float* kvec;
            if (lane < 2)
                kvec = cache_k + (((size_t)(1 + lane) * Bb * NHH + bh) * SS + s) * 64;
            else
                kvec = kcur + (((size_t)b * NKVV + (h >> 2)) * SS + s) * 64;
            float dot = 0.f;
#pragma unroll 8
            for (int d = 0; d < 64; d++) dot += Qs[d][rr] * kvec[d];
            sc[rr][lane] = dot * scale;
        }
    }
    __syncthreads();
    if ((tid & 3) == 0) {
        int rr = lr;
        float mold = m_s[rr];
        float mx = mold;
#pragma unroll
        for (int n = 0; n < 3; n++) mx = fmaxf(mx, sc[rr][n]);
        float sum = 0.f;
#pragma unroll
        for (int n = 0; n < 3; n++) {
            float p = __expf(sc[rr][n] - mx);
            sc[rr][n] = p;
            sum += p;
        }
        float corr = __expf(mold - mx);
        l_s[rr] = l_s[rr] * corr + sum;
        m_s[rr] = mx;
        cr_s[rr] = corr;
    }
    __syncthreads();
#pragma unroll
    for (int i = 0; i < 4; i++) {
        float cf = cr_s[ty * 4 + i];
#pragma unroll
        for (int j = 0; j < 4; j++) acc[i][j] *= cf;
    }
#pragma unroll
    for (int i = 0; i < 4; i++) {
        int s = q0 + ty * 4 + i;
#pragma unroll
        for (int n = 0; n < 3; n++) {
            const float* vvec = (n < 2)
                ? cache_v + (((size_t)(1 + n) * Bb * NHH + bh) * SS + s) * 64
                : vcur + (((size_t)b * NKVV + (h >> 2)) * SS + s) * 64;
            float p = sc[ty * 4 + i][n];
            float4 vv = *(const float4*)(vvec + tx * 4);
            acc[i][0] += p * vv.x; acc[i][1] += p * vv.y;
            acc[i][2] += p * vv.z; acc[i][3] += p * vv.w;
        }
    }
#pragma unroll
    for (int i = 0; i < 4; i++) {
        int s = q0 + ty * 4 + i;
        float inv = 1.0f / l_s[ty * 4 + i];
        size_t oidx = ((size_t)(b * SS + s)) * HH + h * 64 + tx * 4;
#pragma unroll
        for (int j = 0; j < 4; j++) {
            __nv_bfloat16 hv, lv;
            split2(acc[i][j] * inv, hv, lv);
            ohi[oidx + j] = hv;
            olo[oidx + j] = lv;
        }
    }
}

// SiLU(gate)*up -> split bf16 pair
__global__ __launch_bounds__(256) void silu_split_kernel(
    const float* __restrict__ gu, __nv_bfloat16* __restrict__ hi,
    __nv_bfloat16* __restrict__ lo)
{
    int i = blockIdx.x * 256 + threadIdx.x;   // over TOK*IIF
    int row = i >> 13, col = i & 8191;
    float g = gu[(size_t)row * 16384 + col];
    float u = gu[(size_t)row * 16384 + 8192 + col];
    float a = g / (1.0f + expf(-g)) * u;
    __nv_bfloat16 hv, lv;
    split2(a, hv, lv);
    hi[i] = hv; lo[i] = lv;
}

// ================= launcher =================
extern "C" void kernel_launch(void* const* d_in, const int* in_sizes, int n_in,
                              void* d_out, int out_size)
{
    const float* input_emb     = (const float*)d_in[0];
    const float* hidden_states = (const float*)d_in[1];
    const float* cache_k       = (const float*)d_in[2];
    const float* cache_v       = (const float*)d_in[3];
    const int*   position_ids  = (const int*)d_in[5];
    const float* wq            = (const float*)d_in[6];
    const float* wk            = (const float*)d_in[7];
    const float* wv            = (const float*)d_in[8];
    const float* wo            = (const float*)d_in[9];
    const float* w_gate        = (const float*)d_in[10];
    const float* w_up          = (const float*)d_in[11];
    const float* w_down        = (const float*)d_in[12];
    const float* hidden_norm_w = (const float*)d_in[13];
    const float* input_ln_w    = (const float*)d_in[14];
    const float* post_ln_w     = (const float*)d_in[15];
    float* out = (float*)d_out;

    __nv_bfloat16 *xhi, *xlo, *wqkvh, *wqkvl, *woh, *wol, *wguh, *wgul, *wdnh, *wdnl;
    __nv_bfloat16 *ahi, *alo, *hnhi, *hnlo, *acth, *actl;
    float *qkv, *q, *k, *v, *h2, *gu;
    cudaGetSymbolAddress((void**)&xhi, g_xhi);     cudaGetSymbolAddress((void**)&xlo, g_xlo);
    cudaGetSymbolAddress((void**)&wqkvh, g_wqkv_hi); cudaGetSymbolAddress((void**)&wqkvl, g_wqkv_lo);
    cudaGetSymbolAddress((void**)&woh, g_wo_hi);   cudaGetSymbolAddress((void**)&wol, g_wo_lo);
    cudaGetSymbolAddress((void**)&wguh, g_wgu_hi); cudaGetSymbolAddress((void**)&wgul, g_wgu_lo);
    cudaGetSymbolAddress((void**)&wdnh, g_wdn_hi); cudaGetSymbolAddress((void**)&wdnl, g_wdn_lo);
    cudaGetSymbolAddress((void**)&ahi, g_ahi);     cudaGetSymbolAddress((void**)&alo, g_alo);
    cudaGetSymbolAddress((void**)&hnhi, g_hnhi);   cudaGetSymbolAddress((void**)&hnlo, g_hnlo);
    cudaGetSymbolAddress((void**)&acth, g_acthi);  cudaGetSymbolAddress((void**)&actl, g_actlo);
    cudaGetSymbolAddress((void**)&qkv, g_qkv);
    cudaGetSymbolAddress((void**)&q, g_q);
    cudaGetSymbolAddress((void**)&k, g_k);
    cudaGetSymbolAddress((void**)&v, g_v);
    cudaGetSymbolAddress((void**)&h2, g_h2);
    cudaGetSymbolAddress((void**)&gu, g_gu);

    cudaFuncSetAttribute(gemm_mma, cudaFuncAttributeMaxDynamicSharedMemorySize, GEMM_DSMEM);
    const int attn_smem = (4 * 64 * 68 + 3 * 64) * (int)sizeof(float);
    cudaFuncSetAttribute(attn_kernel, cudaFuncAttributeMaxDynamicSharedMemorySize, attn_smem);

    // weight conversions (fp32 -> bf16 hi/lo), packed QKV and gate|up
    convert_split_kernel<<<2048 * 4096 / 1024, 256>>>(wq, wqkvh, wqkvl, 2048 * 4096);
    convert_split_kernel<<<512 * 4096 / 1024, 256>>>(wk, wqkvh + 2048 * 4096, wqkvl + 2048 * 4096, 512 * 4096);
    convert_split_kernel<<<512 * 4096 / 1024, 256>>>(wv, wqkvh + 2560 * 4096, wqkvl + 2560 * 4096, 512 * 4096);
    convert_split_kernel<<<2048 * 2048 / 1024, 256>>>(wo, woh, wol, 2048 * 2048);
    convert_split_kernel<<<8192 * 2048 / 1024, 256>>>(w_gate, wguh, wgul, 8192 * 2048);
    convert_split_kernel<<<8192 * 2048 / 1024, 256>>>(w_up, wguh + 8192 * 2048, wgul + 8192 * 2048, 8192 * 2048);
    convert_split_kernel<<<2048 * 8192 / 1024, 256>>>(w_down, wdnh, wdnl, 2048 * 8192);

    // 1. norms + concat (split bf16)
    rmsnorm_concat_kernel<<<TOK, 256>>>(input_emb, hidden_states, input_ln_w, hidden_norm_w, xhi, xlo);
    // 2. QKV GEMM (packed, N=3072)
    gemm_mma<<<dim3(3072 / 128, TOK / 128), 256, GEMM_DSMEM>>>(xhi, xlo, wqkvh, wqkvl, nullptr, qkv, 3072, 4096, 0);
    // 3. RoPE + reshape
    rope_kernel<<<TOK, 256>>>(qkv, position_ids, q, k, v);
    // 4. attention -> split bf16
    attn_kernel<<<dim3(SS / 64, NHH, Bb), 256, attn_smem>>>(q, cache_k, cache_v, k, v, ahi, alo);
    // 5. out projection + residual
    gemm_mma<<<dim3(2048 / 128, TOK / 128), 256, GEMM_DSMEM>>>(ahi, alo, woh, wol, hidden_states, h2, 2048, 2048, 1);
    // 6. post-attn norm -> split bf16
    rmsnorm_split_kernel<<<TOK, 256>>>(h2, post_ln_w, hnhi, hnlo);
    // 7. gate|up GEMM (packed, N=16384)
    gemm_mma<<<dim3(16384 / 128, TOK / 128), 256, GEMM_DSMEM>>>(hnhi, hnlo, wguh, wgul, nullptr, gu, 16384, 2048, 0);
    // 8. SiLU * up -> split bf16
    silu_split_kernel<<<TOK * IIF / 256, 256>>>(gu, acth, actl);
    // 9. down projection + residual -> final output
    gemm_mma<<<dim3(2048 / 128, TOK / 128), 256, GEMM_DSMEM>>>(acth, actl, wdnh, wdnl, h2, out, 2048, 8192, 1);

    (void)in_sizes; (void)n_in; (void)out_size;
}